// round 17
// baseline (speedup 1.0000x reference)
#include <cuda_runtime.h>
#include <cstdint>

#define H 4096
#define E 8
#define H4 1024                 // float4 per row
#define TPB 256
#define ITERS (H4 / TPB)        // 4
#define NPREF 140               // prefetch-helper blocks in router kernel
#define PREF_ROWS 1024          // prefetch first 16 MB of gate_w (1024 rows)

__device__ unsigned long long g_best;  // (sortable_logit << 32) | (7 - e)
__device__ int g_rcnt;
__device__ int g_idx;

__device__ __forceinline__ unsigned int f2sortable(float f) {
    unsigned int u = __float_as_uint(f);
    return (u & 0x80000000u) ? ~u : (u | 0x80000000u);
}

// ---- Kernel 1: blocks 0..7 router (one expert each); blocks 8..147 warm L2
//      with the head of gate_w during the otherwise DRAM-idle router window.
__global__ void __launch_bounds__(TPB) router_kernel(
        const float* __restrict__ x,
        const float* __restrict__ router_w,
        const float* __restrict__ router_b,
        const float* __restrict__ gate_w) {
    const int wid  = threadIdx.x >> 5;
    const int lane = threadIdx.x & 31;

    if (blockIdx.x >= E) {
        // L2 prefetch helpers: ~7.4 rows per block of gate_w's first PREF_ROWS.
        const int pb = blockIdx.x - E;
        const size_t total_lines = (size_t)PREF_ROWS * H * 4 / 128;  // 128B lines
        const size_t lines_per_block = (total_lines + NPREF - 1) / NPREF;
        const size_t start = pb * lines_per_block;
        const size_t end = (start + lines_per_block < total_lines)
                               ? start + lines_per_block : total_lines;
        for (size_t l = start + threadIdx.x; l < end; l += TPB) {
            const char* p = (const char*)gate_w + l * 128;
            asm volatile("prefetch.global.L2 [%0];" :: "l"(p));
        }
        cudaTriggerProgrammaticLaunchCompletion();
        return;
    }

    const int e = blockIdx.x;
    const float4* x4 = (const float4*)x;
    const float4* w4 = (const float4*)(router_w + (size_t)e * H);

    float s = 0.f;
    #pragma unroll
    for (int k = 0; k < ITERS; k++) {
        int i = threadIdx.x + k * TPB;
        float4 a = __ldcg(x4 + i);
        float4 b = __ldcg(w4 + i);
        s += a.x * b.x + a.y * b.y + a.z * b.z + a.w * b.w;
    }
    #pragma unroll
    for (int o = 16; o > 0; o >>= 1) s += __shfl_xor_sync(0xFFFFFFFFu, s, o);

    __shared__ float s_red[TPB / 32];
    if (lane == 0) s_red[wid] = s;
    __syncthreads();
    if (threadIdx.x == 0) {
        float v = router_b[e];
        #pragma unroll
        for (int w = 0; w < TPB / 32; w++) v += s_red[w];
        unsigned long long key =
            ((unsigned long long)f2sortable(v) << 32) | (unsigned long long)(7 - e);
        atomicMax(&g_best, key);
        __threadfence();
        int r = atomicAdd(&g_rcnt, 1);
        if (r == E - 1) {                      // last router block: decode + reset
            __threadfence();
            unsigned long long b = atomicAdd(&g_best, 0ULL);
            g_idx = 7 - (int)(b & 7ULL);
            g_best = 0ULL;
            g_rcnt = 0;
            __threadfence();
        }
    }
    cudaTriggerProgrammaticLaunchCompletion();
}

// ---- Kernel 2: R2 shape, PDL wait at entry, streaming loads via __ldcg.
__global__ void __launch_bounds__(TPB) gate_mix_kernel(
    const float* __restrict__ x,
    const float* __restrict__ expert_w,
    const float* __restrict__ expert_b,
    const float* __restrict__ gate_w,
    const float* __restrict__ gate_b,
    float* __restrict__ out) {

    cudaGridDependencySynchronize();

    const int row = blockIdx.x;
    const int idx = g_idx;

    const float4* x4 = (const float4*)x;
    const float4* e4 = (const float4*)(expert_w + ((size_t)idx * H + row) * H);
    const float4* g4 = (const float4*)(gate_w + (size_t)row * H);

    // Batch all 12 loads up front; weights bypass L1 allocation (.cg).
    float4 xa[ITERS], ea[ITERS], ga[ITERS];
    #pragma unroll
    for (int k = 0; k < ITERS; k++) {
        int i = threadIdx.x + k * TPB;
        xa[k] = __ldca(x4 + i);     // x reused across blocks: keep in L1
        ea[k] = __ldcg(e4 + i);     // stream
        ga[k] = __ldcg(g4 + i);     // stream
    }

    float se = 0.f, sg = 0.f;
    #pragma unroll
    for (int k = 0; k < ITERS; k++) {
        se += xa[k].x * ea[k].x + xa[k].y * ea[k].y
            + xa[k].z * ea[k].z + xa[k].w * ea[k].w;
        sg += xa[k].x * ga[k].x + xa[k].y * ga[k].y
            + xa[k].z * ga[k].z + xa[k].w * ga[k].w;
    }

    #pragma unroll
    for (int o = 16; o > 0; o >>= 1) {
        se += __shfl_xor_sync(0xFFFFFFFFu, se, o);
        sg += __shfl_xor_sync(0xFFFFFFFFu, sg, o);
    }

    __shared__ float re[TPB / 32], rg[TPB / 32];
    const int wid  = threadIdx.x >> 5;
    const int lane = threadIdx.x & 31;
    if (lane == 0) { re[wid] = se; rg[wid] = sg; }
    __syncthreads();

    if (threadIdx.x == 0) {
        float SE = 0.f, SG = 0.f;
        #pragma unroll
        for (int w = 0; w < TPB / 32; w++) { SE += re[w]; SG += rg[w]; }
        float mix = tanhf(SE + expert_b[(size_t)idx * H + row]);
        float z = SG + gate_b[row];
        float g = 1.f / (1.f + expf(-z));
        float xv = x[row];
        out[row] = g * mix + (1.f - g) * xv;
    }
}

extern "C" void kernel_launch(void* const* d_in, const int* in_sizes, int n_in,
                              void* d_out, int out_size) {
    const float* x        = (const float*)d_in[0];  // [1, H]
    const float* expert_w = (const float*)d_in[1];  // [E, H, H]
    const float* expert_b = (const float*)d_in[2];  // [E, H]
    const float* router_w = (const float*)d_in[3];  // [E, H]
    const float* router_b = (const float*)d_in[4];  // [E]
    const float* gate_w   = (const float*)d_in[5];  // [H, H]
    const float* gate_b   = (const float*)d_in[6];  // [H]
    float* out = (float*)d_out;                     // [1, H]

    router_kernel<<<E + NPREF, TPB>>>(x, router_w, router_b, gate_w);

    cudaLaunchConfig_t cfg = {};
    cfg.gridDim  = dim3(H, 1, 1);
    cfg.blockDim = dim3(TPB, 1, 1);
    cfg.dynamicSmemBytes = 0;
    cudaLaunchAttribute attr[1];
    attr[0].id = cudaLaunchAttributeProgrammaticStreamSerialization;
    attr[0].val.programmaticStreamSerializationAllowed = 1;
    cfg.attrs = attr;
    cfg.numAttrs = 1;
    cudaLaunchKernelEx(&cfg, gate_mix_kernel,
                       x, expert_w, expert_b, gate_w, gate_b, out);
}